// round 14
// baseline (speedup 1.0000x reference)
#include <cuda_runtime.h>

typedef unsigned long long u64;

#define NBINS  4
#define NFEAT  48
#define KTOT   2048
#define NT     16            // batch rows per unit
#define TLEN   154
#define OUTF   (NBINS * NFEAT)
#define CHUNKK 256           // pooled k per chunk
#define CPU    8             // chunks per unit
#define UNITF  32768         // floats per unit in g_pooled
#define MAXUNITS 512         // supports ntot <= 2048

__device__ float g_Weff[NBINS * NFEAT * KTOT];        // [bf][k]
__device__ float g_pooled[MAXUNITS * UNITF];          // staged pooled data

__constant__ float c_dec_lo[8] = {
    -0.010597401784997278f,  0.032883011666982945f,  0.030841381835986965f,
    -0.18703481171888114f,  -0.02798376941698385f,   0.6308807679295904f,
     0.7148465705525415f,    0.23037781330885523f };
__constant__ float c_dec_hi[8] = {
    -0.23037781330885523f,   0.7148465705525415f,   -0.6308807679295904f,
    -0.02798376941698385f,   0.18703481171888114f,   0.030841381835986965f,
    -0.032883011666982945f, -0.010597401784997278f };

__device__ __forceinline__ u64 ffma2(u64 a, u64 b, u64 c) {
    u64 d; asm("fma.rn.f32x2 %0, %1, %2, %3;" : "=l"(d) : "l"(a), "l"(b), "l"(c));
    return d;
}
__device__ __forceinline__ u64 fadd2(u64 a, u64 b) {
    u64 d; asm("add.rn.f32x2 %0, %1, %2;" : "=l"(d) : "l"(a), "l"(b));
    return d;
}
__device__ __forceinline__ u64 dup2(float x) {
    u64 d; asm("mov.b64 %0, {%1, %1};" : "=l"(d) : "f"(x));
    return d;
}
__device__ __forceinline__ float2 unpack2(u64 a) {
    float2 v; asm("mov.b64 {%0, %1}, %2;" : "=f"(v.x), "=f"(v.y) : "l"(a));
    return v;
}
__device__ __forceinline__ int refl(int r, int N) {
    if (r < 0) r = -r;
    else if (r >= N) r = 2 * N - 2 - r;
    return r;
}

// ============================================================
// Fused weight builder (unchanged; ~3us).
// ============================================================
__global__ void build_weff_fused(const float* __restrict__ conv_w) {
    __shared__ float A[68 * 16];
    __shared__ float B[38 * 16];
    __shared__ float Mt[TLEN * 16];
    __shared__ float Ws[TLEN * 16];
    const int tid = threadIdx.x;
    const int bf = blockIdx.x;
    const int kc = blockIdx.y;

    for (int i = tid; i < TLEN * 16; i += 256)
        Ws[i] = conv_w[(size_t)bf * (TLEN * 16) + i];

    const int sl = tid & 15;
    const int ip = tid >> 4;
    const int j  = kc * 16 + sl;

    for (int i = ip; i < 67; i += 16) {
        float a0 = 0.0f, a1 = 0.0f;
        #pragma unroll
        for (int u = 0; u < 8; ++u) {
            int r = refl(2 * i + u - 6, 128);
            if (r == j) { a0 += c_dec_lo[7 - u]; a1 += c_dec_hi[7 - u]; }
        }
        A[i * 16 + sl] = a0;
        Mt[(14 + i) * 16 + sl] = a1;
    }
    __syncthreads();
    for (int i = ip; i < 37; i += 16) {
        float a0 = 0.0f, a1 = 0.0f;
        #pragma unroll
        for (int u = 0; u < 8; ++u) {
            int r = refl(2 * i + u - 6, 67);
            float xv = A[r * 16 + sl];
            a0 += xv * c_dec_lo[7 - u];
            a1 += xv * c_dec_hi[7 - u];
        }
        B[i * 16 + sl] = a0;
        Mt[(81 + i) * 16 + sl] = a1;
    }
    __syncthreads();
    for (int i = ip; i < 22; i += 16) {
        float a0 = 0.0f, a1 = 0.0f;
        #pragma unroll
        for (int u = 0; u < 8; ++u) {
            int r = refl(2 * i + u - 6, 37);
            float xv = B[r * 16 + sl];
            a0 += xv * c_dec_lo[7 - u];
            a1 += xv * c_dec_hi[7 - u];
        }
        A[i * 16 + sl] = a0;
        Mt[(118 + i) * 16 + sl] = a1;
    }
    __syncthreads();
    for (int i = ip; i < 14; i += 16) {
        float a0 = 0.0f, a1 = 0.0f;
        #pragma unroll
        for (int u = 0; u < 8; ++u) {
            int r = refl(2 * i + u - 6, 22);
            float xv = A[r * 16 + sl];
            a0 += xv * c_dec_lo[7 - u];
            a1 += xv * c_dec_hi[7 - u];
        }
        Mt[i * 16 + sl] = a0;
        Mt[(140 + i) * 16 + sl] = a1;
    }
    __syncthreads();

    const int scol = tid >> 4;
    const int hw   = tid & 15;
    float acc = 0.0f;
    #pragma unroll 7
    for (int t = 0; t < TLEN; ++t)
        acc += Mt[t * 16 + scol] * Ws[t * 16 + hw];
    g_Weff[(size_t)bf * KTOT + kc * 256 + tid] = acc;
}

// ============================================================
// Kernel A: streaming maxpool. Persistent grid-stride over
// chunk index C = unit*8 + ci. 256 threads; per thread 16
// front-batched LDG.128, shfl-pool, owner STG.128 per np.
// Output layout per chunk (4096 floats at g_pooled +
// unit*32768 + ci*4096): [np*512 + 2*k + hal], k0 even.
// ============================================================
__global__ __launch_bounds__(256, 3)
void pool_kernel(const float* __restrict__ x, int ntot, int groups)
{
    const int tid = threadIdx.x;
    const int totC = NBINS * groups * CPU;
    const int tl = tid >> 4, h = (tid >> 2) & 3, qh = tid & 1;
    const int k0 = tl * 16 + h * 4 + 2 * qh;    // even, 0..254
    const bool owner = ((tid & 2) == 0);

    for (int C = blockIdx.x; C < totC; C += gridDim.x) {
        const int unit = C >> 3, ci = C & 7;
        const int b = unit / groups, g = unit % groups;
        const int n0 = g * NT;

        float4 v0[8], v1[8];
        #pragma unroll
        for (int np = 0; np < 8; ++np) {
            int ne = n0 + 2 * np, no = ne + 1;
            if (ne >= ntot) ne = ntot - 1;
            if (no >= ntot) no = ntot - 1;
            const float4* xg0 = reinterpret_cast<const float4*>(
                x + ((size_t)ne * 512 + b * 128 + ci * 16) * 64);
            const float4* xg1 = reinterpret_cast<const float4*>(
                x + ((size_t)no * 512 + b * 128 + ci * 16) * 64);
            v0[np] = xg0[tid];
            v1[np] = xg1[tid];
        }

        float* gbuf = g_pooled + (size_t)unit * UNITF + ci * 4096;
        #pragma unroll
        for (int np = 0; np < 8; ++np) {
            float a0 = fmaxf(v0[np].x, v0[np].y), c0 = fmaxf(v0[np].z, v0[np].w);
            float a1 = fmaxf(v1[np].x, v1[np].y), c1 = fmaxf(v1[np].z, v1[np].w);
            a0 = fmaxf(a0, __shfl_xor_sync(0xffffffffu, a0, 2));
            c0 = fmaxf(c0, __shfl_xor_sync(0xffffffffu, c0, 2));
            a1 = fmaxf(a1, __shfl_xor_sync(0xffffffffu, a1, 2));
            c1 = fmaxf(c1, __shfl_xor_sync(0xffffffffu, c1, 2));
            if (owner)
                *reinterpret_cast<float4*>(gbuf + np * 512 + 2 * k0) =
                    make_float4(a0, a1, c0, c1);
        }
    }
}

// ============================================================
// Kernel B: GEMV. 512 blocks (one per unit) x 1024 threads.
// 32 warps = 16 feature-groups (3 feats) x 2 n-halves (4 planes).
// cp.async stages pooled data (3-deep, 16KB each) and weights
// (2-deep, 48KB each) -> inner loop is pure LDS + FFMA2.
// smem: dat[3*4096] | wt[2*12288] = 144KB.
// ============================================================
#define DAT0 0
#define WT0  (3 * 4096)
#define B_SMEMF (3 * 4096 + 2 * 12288)

__global__ __launch_bounds__(1024, 1)
void gemv_kernel(const float* __restrict__ conv_b,
                 float* __restrict__ out, int ntot, int groups)
{
    extern __shared__ float sm[];
    const int tid  = threadIdx.x;
    const int warp = tid >> 5;
    const int lane = tid & 31;
    const int fg    = warp & 15;      // feature group (3 feats)
    const int nhalf = warp >> 4;      // 0: planes 0..3, 1: planes 4..7
    const int unit = blockIdx.x;
    const int b = unit / groups;
    const int g = unit % groups;

    const unsigned sbase = (unsigned)__cvta_generic_to_shared(sm);
    const float4* psrc = reinterpret_cast<const float4*>(
        g_pooled + (size_t)unit * UNITF);
    const float4* wsrc = reinterpret_cast<const float4*>(g_Weff);

    // ---- cp.async issue helpers ----
    auto issue_data = [&](int c) {
        unsigned dst = sbase + (((c % 3) * 4096 + 4 * tid) << 2);
        const float4* src = psrc + c * 1024 + tid;
        asm volatile("cp.async.cg.shared.global [%0], [%1], 16;"
                     :: "r"(dst), "l"(src));
    };
    auto issue_wt = [&](int c) {
        #pragma unroll
        for (int i = 0; i < 3; ++i) {
            int jj = tid + 1024 * i;          // 0..3071
            int f = jj >> 6, col = jj & 63;
            unsigned dst = sbase + ((WT0 + (c & 1) * 12288 + 4 * jj) << 2);
            const float4* src = wsrc + (size_t)(b * NFEAT + f) * (KTOT / 4)
                                + c * 64 + col;
            asm volatile("cp.async.cg.shared.global [%0], [%1], 16;"
                         :: "r"(dst), "l"(src));
        }
    };

    u64 acc[3][4];
    #pragma unroll
    for (int f = 0; f < 3; ++f)
        #pragma unroll
        for (int p = 0; p < 4; ++p) acc[f][p] = 0ull;

    // prologue: groups {d0,w0}, {d1,w1}, {d2}
    issue_data(0); issue_wt(0);
    asm volatile("cp.async.commit_group;");
    issue_data(1); issue_wt(1);
    asm volatile("cp.async.commit_group;");
    issue_data(2);
    asm volatile("cp.async.commit_group;");

    for (int ci = 0; ci < CPU; ++ci) {
        asm volatile("cp.async.wait_group 2;");
        __syncthreads();

        const float* dbase = sm + (ci % 3) * 4096 + nhalf * 2048 + 2 * lane;
        const float* wrow  = sm + WT0 + (ci & 1) * 12288 + (fg * 3) * 256 + lane;

        float w0[3], w1[3];
        #pragma unroll
        for (int f = 0; f < 3; ++f) w0[f] = wrow[f * 256];
        #pragma unroll
        for (int f = 0; f < 3; ++f) w1[f] = wrow[f * 256 + 32];

        #pragma unroll 1
        for (int jl = 0; jl < 8; jl += 2) {
            {   // even jl
                u64 p2[4];
                #pragma unroll
                for (int pl = 0; pl < 4; ++pl)
                    p2[pl] = *reinterpret_cast<const u64*>(
                        dbase + pl * 512 + 64 * jl);
                float a0 = w0[0], a1 = w0[1], a2 = w0[2];
                if (jl + 2 < 8) {
                    #pragma unroll
                    for (int f = 0; f < 3; ++f)
                        w0[f] = wrow[f * 256 + 32 * (jl + 2)];
                }
                u64 d0 = dup2(a0), d1 = dup2(a1), d2 = dup2(a2);
                #pragma unroll
                for (int pl = 0; pl < 4; ++pl) {
                    acc[0][pl] = ffma2(d0, p2[pl], acc[0][pl]);
                    acc[1][pl] = ffma2(d1, p2[pl], acc[1][pl]);
                    acc[2][pl] = ffma2(d2, p2[pl], acc[2][pl]);
                }
            }
            {   // odd jl
                u64 p2[4];
                #pragma unroll
                for (int pl = 0; pl < 4; ++pl)
                    p2[pl] = *reinterpret_cast<const u64*>(
                        dbase + pl * 512 + 64 * (jl + 1));
                float a0 = w1[0], a1 = w1[1], a2 = w1[2];
                if (jl + 3 < 8) {
                    #pragma unroll
                    for (int f = 0; f < 3; ++f)
                        w1[f] = wrow[f * 256 + 32 * (jl + 3)];
                }
                u64 d0 = dup2(a0), d1 = dup2(a1), d2 = dup2(a2);
                #pragma unroll
                for (int pl = 0; pl < 4; ++pl) {
                    acc[0][pl] = ffma2(d0, p2[pl], acc[0][pl]);
                    acc[1][pl] = ffma2(d1, p2[pl], acc[1][pl]);
                    acc[2][pl] = ffma2(d2, p2[pl], acc[2][pl]);
                }
            }
        }

        __syncthreads();
        if (ci + 3 < CPU) issue_data(ci + 3);
        if (ci + 2 < CPU) issue_wt(ci + 2);
        asm volatile("cp.async.commit_group;");
    }

    // ---- epilogue: butterfly reduce + bias + leaky + store ----
    #pragma unroll
    for (int off = 16; off; off >>= 1)
        #pragma unroll
        for (int f = 0; f < 3; ++f)
            #pragma unroll
            for (int pl = 0; pl < 4; ++pl)
                acc[f][pl] = fadd2(acc[f][pl],
                    __shfl_xor_sync(0xffffffffu, acc[f][pl], off));

    if (lane == 0) {
        const int n0 = g * NT + nhalf * 8;
        #pragma unroll
        for (int f = 0; f < 3; ++f) {
            int fgl = fg * 3 + f;
            float bias = conv_b[b * NFEAT + fgl];
            #pragma unroll
            for (int pl = 0; pl < 4; ++pl) {
                float2 v = unpack2(acc[f][pl]);
                int na = n0 + 2 * pl;
                float ya = v.x + bias; ya = (ya > 0.0f) ? ya : 0.02f * ya;
                float yb = v.y + bias; yb = (yb > 0.0f) ? yb : 0.02f * yb;
                if (na < ntot)
                    out[(size_t)na * OUTF + b * NFEAT + fgl] = ya;
                if (na + 1 < ntot)
                    out[(size_t)(na + 1) * OUTF + b * NFEAT + fgl] = yb;
            }
        }
    }
}

// ============================================================
extern "C" void kernel_launch(void* const* d_in, const int* in_sizes, int n_in,
                              void* d_out, int out_size)
{
    const float* x      = (const float*)d_in[0];  // (n,1,512,8,8)
    const float* conv_w = (const float*)d_in[1];  // (4,48,154,4,4)
    const float* conv_b = (const float*)d_in[2];  // (4,48)
    float* out = (float*)d_out;                   // (n,192)

    int ntot   = in_sizes[0] / (512 * 64);
    int groups = (ntot + NT - 1) / NT;

    dim3 wgrid(NBINS * NFEAT, KTOT / 256);
    build_weff_fused<<<wgrid, 256>>>(conv_w);

    pool_kernel<<<444, 256>>>(x, ntot, groups);

    cudaFuncSetAttribute(gemv_kernel,
                         cudaFuncAttributeMaxDynamicSharedMemorySize,
                         B_SMEMF * 4);
    gemv_kernel<<<NBINS * groups, 1024, B_SMEMF * 4>>>(conv_b, out, ntot, groups);
}

// round 15
// speedup vs baseline: 1.1486x; 1.1486x over previous
#include <cuda_runtime.h>

typedef unsigned long long u64;

#define NBINS  4
#define NFEAT  48
#define KTOT   2048
#define NT     16            // batch rows per unit
#define TLEN   154
#define OUTF   (NBINS * NFEAT)
#define NCTAS  148
#define CHUNKK 512           // pooled k per chunk
#define SLOTF  (CHUNKK * 16) // floats per slot: 512 k * 16 n = 8192 (32KB)
#define NSLOTS 4
#define CPU    4             // chunks per unit = KTOT / CHUNKK
#define NTHREADS 768         // 16 consumer warps + 8 producer warps

// named barrier ids: full[s] = 1+s, empty[s] = 5+s
#define BAR_SYNC(id)   asm volatile("bar.sync %0, %1;"   :: "r"(id), "r"(NTHREADS) : "memory")
#define BAR_ARRIVE(id) asm volatile("bar.arrive %0, %1;" :: "r"(id), "r"(NTHREADS) : "memory")

__device__ float g_M[TLEN * 128];               // DWT matrix [t][s]
__device__ float g_Weff[NBINS * NFEAT * KTOT];  // [bf][k]

__constant__ float c_dec_lo[8] = {
    -0.010597401784997278f,  0.032883011666982945f,  0.030841381835986965f,
    -0.18703481171888114f,  -0.02798376941698385f,   0.6308807679295904f,
     0.7148465705525415f,    0.23037781330885523f };
__constant__ float c_dec_hi[8] = {
    -0.23037781330885523f,   0.7148465705525415f,   -0.6308807679295904f,
    -0.02798376941698385f,   0.18703481171888114f,   0.030841381835986965f,
    -0.032883011666982945f, -0.010597401784997278f };

__device__ __forceinline__ u64 ffma2(u64 a, u64 b, u64 c) {
    u64 d; asm("fma.rn.f32x2 %0, %1, %2, %3;" : "=l"(d) : "l"(a), "l"(b), "l"(c));
    return d;
}
__device__ __forceinline__ u64 fadd2(u64 a, u64 b) {
    u64 d; asm("add.rn.f32x2 %0, %1, %2;" : "=l"(d) : "l"(a), "l"(b));
    return d;
}
__device__ __forceinline__ u64 dup2(float x) {
    u64 d; asm("mov.b64 %0, {%1, %1};" : "=l"(d) : "f"(x));
    return d;
}
__device__ __forceinline__ float2 unpack2(u64 a) {
    float2 v; asm("mov.b64 {%0, %1}, %2;" : "=f"(v.x), "=f"(v.y) : "l"(a));
    return v;
}
__device__ __forceinline__ int refl(int r, int N) {
    if (r < 0) r = -r;
    else if (r >= N) r = 2 * N - 2 - r;
    return r;
}

// ============================================================
// Step 1: build the 154x128 DWT matrix ONCE. 1 block x 1024
// threads, level buffers in dynamic smem (53KB).
// Levels: N {128,67,37,22} -> out {67,37,22,14}; left pad 6;
// concat offsets: lo4 @0, hi1 @14, hi2 @81, hi3 @118, hi4 @140.
// ============================================================
__global__ void build_M_kernel() {
    extern __shared__ float smA[];        // A: 67*128, B: 37*128
    float* A = smA;
    float* B = smA + 67 * 128;
    const int tid = threadIdx.x;
    const int NTH = 1024;

    // level 1 from implicit identity
    for (int idx = tid; idx < 67 * 128; idx += NTH) {
        int i = idx >> 7, j = idx & 127;
        float a0 = 0.0f, a1 = 0.0f;
        #pragma unroll
        for (int u = 0; u < 8; ++u) {
            int r = refl(2 * i + u - 6, 128);
            if (r == j) { a0 += c_dec_lo[7 - u]; a1 += c_dec_hi[7 - u]; }
        }
        A[idx] = a0;
        g_M[(14 + i) * 128 + j] = a1;
    }
    __syncthreads();
    // level 2: A(67) -> B(37), hi @81
    for (int idx = tid; idx < 37 * 128; idx += NTH) {
        int i = idx >> 7, j = idx & 127;
        float a0 = 0.0f, a1 = 0.0f;
        #pragma unroll
        for (int u = 0; u < 8; ++u) {
            int r = refl(2 * i + u - 6, 67);
            float xv = A[r * 128 + j];
            a0 += xv * c_dec_lo[7 - u];
            a1 += xv * c_dec_hi[7 - u];
        }
        B[idx] = a0;
        g_M[(81 + i) * 128 + j] = a1;
    }
    __syncthreads();
    // level 3: B(37) -> A(22), hi @118
    for (int idx = tid; idx < 22 * 128; idx += NTH) {
        int i = idx >> 7, j = idx & 127;
        float a0 = 0.0f, a1 = 0.0f;
        #pragma unroll
        for (int u = 0; u < 8; ++u) {
            int r = refl(2 * i + u - 6, 37);
            float xv = B[r * 128 + j];
            a0 += xv * c_dec_lo[7 - u];
            a1 += xv * c_dec_hi[7 - u];
        }
        A[idx] = a0;
        g_M[(118 + i) * 128 + j] = a1;
    }
    __syncthreads();
    // level 4: A(22) -> lo @0 (14 rows), hi @140
    for (int idx = tid; idx < 14 * 128; idx += NTH) {
        int i = idx >> 7, j = idx & 127;
        float a0 = 0.0f, a1 = 0.0f;
        #pragma unroll
        for (int u = 0; u < 8; ++u) {
            int r = refl(2 * i + u - 6, 22);
            float xv = A[r * 128 + j];
            a0 += xv * c_dec_lo[7 - u];
            a1 += xv * c_dec_hi[7 - u];
        }
        g_M[i * 128 + j] = a0;
        g_M[(140 + i) * 128 + j] = a1;
    }
}

// ============================================================
// Step 2: fold M into conv_w.
// Weff[bf][kc*256+tid] = sum_t M[t][(kc*256+tid)>>4] * conv_w[bf][t][tid&15]
// grid (192, 8), 256 threads, smem-tiled.
// ============================================================
__global__ void fold_weff(const float* __restrict__ conv_w) {
    const int bf = blockIdx.x;
    const int kc = blockIdx.y;
    __shared__ float Ms[TLEN * 16];
    __shared__ float Ws[TLEN * 16];
    const int tid = threadIdx.x;

    for (int i = tid; i < TLEN * 16; i += 256) {
        int t = i >> 4, c = i & 15;
        Ms[i] = g_M[t * 128 + kc * 16 + c];
        Ws[i] = conv_w[(size_t)bf * (TLEN * 16) + i];
    }
    __syncthreads();

    const int sl = tid >> 4;   // s within the 16-chunk
    const int hw = tid & 15;
    float acc = 0.0f;
    #pragma unroll 7
    for (int t = 0; t < TLEN; ++t)
        acc += Ms[t * 16 + sl] * Ws[t * 16 + hw];
    g_Weff[(size_t)bf * KTOT + kc * 256 + tid] = acc;
}

// ============================================================
// Producer pieces (R9 verbatim). One chunk = 512 k x 16 n,
// filled in 2 waves of 4 np, 16 front-batched LDG.128 per wave.
// Slot layout (floats): buf[np*1024 + 2*k + hal], k0 even.
// ============================================================
__device__ __forceinline__ void ldnp(const float* __restrict__ x,
                                     int b, int g, int ci, int ntot,
                                     int ptid, int np,
                                     float4* v0, float4* v1)
{
    int ne = g * NT + 2 * np;
    int no = ne + 1;
    if (ne >= ntot) ne = ntot - 1;
    if (no >= ntot) no = ntot - 1;
    const float4* xg0 = reinterpret_cast<const float4*>(
        x + ((size_t)ne * 512 + b * 128 + ci * 32) * 64);
    const float4* xg1 = reinterpret_cast<const float4*>(
        x + ((size_t)no * 512 + b * 128 + ci * 32) * 64);
    v0[0] = xg0[ptid];       v0[1] = xg0[ptid + 256];
    v1[0] = xg1[ptid];       v1[1] = xg1[ptid + 256];
}

__device__ __forceinline__ void poolstore(float* __restrict__ smp, int ptid,
                                          const float4* v0, const float4* v1)
{
    #pragma unroll
    for (int r = 0; r < 2; ++r) {
        int slot = ptid + 256 * r;
        float a0 = fmaxf(v0[r].x, v0[r].y), c0 = fmaxf(v0[r].z, v0[r].w);
        float a1 = fmaxf(v1[r].x, v1[r].y), c1 = fmaxf(v1[r].z, v1[r].w);
        a0 = fmaxf(a0, __shfl_xor_sync(0xffffffffu, a0, 2));
        c0 = fmaxf(c0, __shfl_xor_sync(0xffffffffu, c0, 2));
        a1 = fmaxf(a1, __shfl_xor_sync(0xffffffffu, a1, 2));
        c1 = fmaxf(c1, __shfl_xor_sync(0xffffffffu, c1, 2));
        if ((slot & 2) == 0) {
            int tl = slot >> 4;
            int h  = (slot >> 2) & 3;
            int qh = slot & 1;
            int k0 = tl * 16 + h * 4 + 2 * qh;
            *reinterpret_cast<float4*>(smp + 2 * k0) =
                make_float4(a0, a1, c0, c1);
        }
    }
}

__device__ __forceinline__ void produce(float* __restrict__ buf,
                                        const float* __restrict__ x,
                                        int b, int g, int ci,
                                        int ntot, int ptid)
{
    #pragma unroll
    for (int wv = 0; wv < 2; ++wv) {
        float4 v0[4][2], v1[4][2];
        #pragma unroll
        for (int i = 0; i < 4; ++i)
            ldnp(x, b, g, ci, ntot, ptid, wv * 4 + i, v0[i], v1[i]);
        #pragma unroll
        for (int i = 0; i < 4; ++i)
            poolstore(buf + (wv * 4 + i) * 1024, ptid, v0[i], v1[i]);
    }
}

// ============================================================
// Main (R9 verbatim): persistent, warp-specialized, 4-slot ring.
// 148 CTAs x 768 threads, 128KB smem.
// Warps 0..15: consumers (3 feats, 8 planes); 16..23: producers.
// ============================================================
__global__ __launch_bounds__(NTHREADS, 1)
void dwt_main_kernel(const float* __restrict__ x,
                     const float* __restrict__ conv_b,
                     float* __restrict__ out, int ntot, int groups)
{
    extern __shared__ float sm[];
    const int tid  = threadIdx.x;
    const int warp = tid >> 5;
    const int lane = tid & 31;
    const int cta  = blockIdx.x;
    const int G    = gridDim.x;
    const int nunits = NBINS * groups;
    const int myUnits = (cta < nunits) ? ((nunits - 1 - cta) / G + 1) : 0;
    const int totalChunks = CPU * myUnits;

    u64 acc[3][8];
    #pragma unroll
    for (int f = 0; f < 3; ++f)
        #pragma unroll
        for (int p = 0; p < 8; ++p) acc[f][p] = 0ull;

    if (warp < 16) {
        #pragma unroll
        for (int s = 0; s < NSLOTS; ++s) BAR_ARRIVE(5 + s);
    }

    if (warp >= 16) {
        // ================= producers =================
        const int ptid = tid - 512;
        for (int sc = 0; sc < totalChunks; ++sc) {
            const int slot = sc & 3;
            const int u  = cta + G * (sc >> 2);
            const int b  = u / groups;
            const int g  = u % groups;
            const int ci = sc & 3;
            BAR_SYNC(5 + slot);
            produce(sm + slot * SLOTF, x, b, g, ci, ntot, ptid);
            BAR_ARRIVE(1 + slot);
        }
    } else {
        // ================= consumers =================
        for (int sc = 0; sc < totalChunks; ++sc) {
            const int slot = sc & 3;
            const int u  = cta + G * (sc >> 2);
            const int b  = u / groups;
            const int g  = u % groups;
            const int ci = sc & 3;
            float* buf = sm + slot * SLOTF;

            BAR_SYNC(1 + slot);

            const float* Wb = g_Weff + ((size_t)(b * NFEAT + warp * 3)) * KTOT
                              + ci * CHUNKK + lane;
            const float* smk = buf + 2 * lane;

            float w0[3], w1[3];
            #pragma unroll
            for (int f = 0; f < 3; ++f) w0[f] = __ldg(Wb + f * KTOT);
            #pragma unroll
            for (int f = 0; f < 3; ++f) w1[f] = __ldg(Wb + f * KTOT + 32);

            #pragma unroll 1
            for (int jl = 0; jl < 16; jl += 2) {
                {   // even jl: use w0, prefetch jl+2
                    u64 p2[8];
                    #pragma unroll
                    for (int pl = 0; pl < 8; ++pl)
                        p2[pl] = *reinterpret_cast<const u64*>(
                            smk + pl * 1024 + 64 * jl);
                    float a0 = w0[0], a1 = w0[1], a2 = w0[2];
                    if (jl + 2 < 16) {
                        #pragma unroll
                        for (int f = 0; f < 3; ++f)
                            w0[f] = __ldg(Wb + f * KTOT + 32 * (jl + 2));
                    }
                    u64 d0 = dup2(a0), d1 = dup2(a1), d2 = dup2(a2);
                    #pragma unroll
                    for (int pl = 0; pl < 8; ++pl) {
                        acc[0][pl] = ffma2(d0, p2[pl], acc[0][pl]);
                        acc[1][pl] = ffma2(d1, p2[pl], acc[1][pl]);
                        acc[2][pl] = ffma2(d2, p2[pl], acc[2][pl]);
                    }
                }
                {   // odd jl: use w1, prefetch jl+3
                    u64 p2[8];
                    #pragma unroll
                    for (int pl = 0; pl < 8; ++pl)
                        p2[pl] = *reinterpret_cast<const u64*>(
                            smk + pl * 1024 + 64 * (jl + 1));
                    float a0 = w1[0], a1 = w1[1], a2 = w1[2];
                    if (jl + 3 < 16) {
                        #pragma unroll
                        for (int f = 0; f < 3; ++f)
                            w1[f] = __ldg(Wb + f * KTOT + 32 * (jl + 3));
                    }
                    u64 d0 = dup2(a0), d1 = dup2(a1), d2 = dup2(a2);
                    #pragma unroll
                    for (int pl = 0; pl < 8; ++pl) {
                        acc[0][pl] = ffma2(d0, p2[pl], acc[0][pl]);
                        acc[1][pl] = ffma2(d1, p2[pl], acc[1][pl]);
                        acc[2][pl] = ffma2(d2, p2[pl], acc[2][pl]);
                    }
                }
            }

            BAR_ARRIVE(5 + slot);

            if (ci == CPU - 1) {
                #pragma unroll
                for (int off = 16; off; off >>= 1)
                    #pragma unroll
                    for (int f = 0; f < 3; ++f)
                        #pragma unroll
                        for (int pl = 0; pl < 8; ++pl)
                            acc[f][pl] = fadd2(acc[f][pl],
                                __shfl_xor_sync(0xffffffffu, acc[f][pl], off));
                if (lane == 0) {
                    int n0 = g * NT;
                    #pragma unroll
                    for (int f = 0; f < 3; ++f) {
                        int fgl = warp * 3 + f;
                        float bias = conv_b[b * NFEAT + fgl];
                        #pragma unroll
                        for (int pl = 0; pl < 8; ++pl) {
                            float2 v = unpack2(acc[f][pl]);
                            int na = n0 + 2 * pl;
                            float ya = v.x + bias; ya = (ya > 0.0f) ? ya : 0.02f * ya;
                            float yb = v.y + bias; yb = (yb > 0.0f) ? yb : 0.02f * yb;
                            if (na < ntot)
                                out[(size_t)na * OUTF + b * NFEAT + fgl] = ya;
                            if (na + 1 < ntot)
                                out[(size_t)(na + 1) * OUTF + b * NFEAT + fgl] = yb;
                        }
                    }
                }
                #pragma unroll
                for (int f = 0; f < 3; ++f)
                    #pragma unroll
                    for (int pl = 0; pl < 8; ++pl) acc[f][pl] = 0ull;
            }
        }
    }
}

// ============================================================
extern "C" void kernel_launch(void* const* d_in, const int* in_sizes, int n_in,
                              void* d_out, int out_size)
{
    const float* x      = (const float*)d_in[0];  // (n,1,512,8,8)
    const float* conv_w = (const float*)d_in[1];  // (4,48,154,4,4)
    const float* conv_b = (const float*)d_in[2];  // (4,48)
    float* out = (float*)d_out;                   // (n,192)

    int ntot   = in_sizes[0] / (512 * 64);
    int groups = (ntot + NT - 1) / NT;

    int mSmem = (67 * 128 + 37 * 128) * 4;  // 53248 B
    cudaFuncSetAttribute(build_M_kernel,
                         cudaFuncAttributeMaxDynamicSharedMemorySize, mSmem);
    build_M_kernel<<<1, 1024, mSmem>>>();

    dim3 fgrid(NBINS * NFEAT, KTOT / 256);
    fold_weff<<<fgrid, 256>>>(conv_w);

    cudaFuncSetAttribute(dwt_main_kernel,
                         cudaFuncAttributeMaxDynamicSharedMemorySize,
                         NSLOTS * SLOTF * 4);
    dwt_main_kernel<<<NCTAS, NTHREADS, NSLOTS * SLOTF * 4>>>(x, conv_b, out, ntot, groups);
}

// round 16
// speedup vs baseline: 1.2421x; 1.0814x over previous
#include <cuda_runtime.h>

typedef unsigned long long u64;

#define NBINS  4
#define NFEAT  48
#define KTOT   2048
#define NT     16            // batch rows per unit
#define TLEN   154
#define OUTF   (NBINS * NFEAT)
#define NCTAS  148
#define CHUNKK 512           // pooled k per chunk
#define SLOTF  (CHUNKK * 16) // floats per slot: 512 k * 16 n = 8192 (32KB)
#define NSLOTS 4
#define CPU    4             // chunks per unit = KTOT / CHUNKK
#define NTHREADS 768         // 16 consumer warps + 8 producer warps

// named barrier ids: full[s] = 1+s, empty[s] = 5+s
#define BAR_SYNC(id)   asm volatile("bar.sync %0, %1;"   :: "r"(id), "r"(NTHREADS) : "memory")
#define BAR_ARRIVE(id) asm volatile("bar.arrive %0, %1;" :: "r"(id), "r"(NTHREADS) : "memory")

__device__ float g_Weff[NBINS * NFEAT * KTOT];  // [bf][k]

__constant__ float c_dec_lo[8] = {
    -0.010597401784997278f,  0.032883011666982945f,  0.030841381835986965f,
    -0.18703481171888114f,  -0.02798376941698385f,   0.6308807679295904f,
     0.7148465705525415f,    0.23037781330885523f };
__constant__ float c_dec_hi[8] = {
    -0.23037781330885523f,   0.7148465705525415f,   -0.6308807679295904f,
    -0.02798376941698385f,   0.18703481171888114f,   0.030841381835986965f,
    -0.032883011666982945f, -0.010597401784997278f };

__device__ __forceinline__ u64 ffma2(u64 a, u64 b, u64 c) {
    u64 d; asm("fma.rn.f32x2 %0, %1, %2, %3;" : "=l"(d) : "l"(a), "l"(b), "l"(c));
    return d;
}
__device__ __forceinline__ u64 fadd2(u64 a, u64 b) {
    u64 d; asm("add.rn.f32x2 %0, %1, %2;" : "=l"(d) : "l"(a), "l"(b));
    return d;
}
__device__ __forceinline__ u64 dup2(float x) {
    u64 d; asm("mov.b64 %0, {%1, %1};" : "=l"(d) : "f"(x));
    return d;
}
__device__ __forceinline__ float2 unpack2(u64 a) {
    float2 v; asm("mov.b64 {%0, %1}, %2;" : "=f"(v.x), "=f"(v.y) : "l"(a));
    return v;
}

// ============================================================
// Adjoint of one analysis level, output element (j, hw).
// Forward: y[i] = sum_u xp[2i+u] * DEC[7-u], xp = reflect-pad
// with left pad 6. Adjoint preimages of output index j are
// r in {j, -j (j in 1..6), 2N-2-j (j <= N-2)}, r = 2i+u-6.
// lo/hi are smem buffers with 16-float (hw) stride.
// ============================================================
__device__ __forceinline__ float adj_level(const float* __restrict__ lo,
                                           const float* __restrict__ hi,
                                           int N, int out, int j, int hw)
{
    float acc = 0.0f;
    #pragma unroll
    for (int u = 0; u < 8; ++u) {
        const float f0 = c_dec_lo[7 - u];
        const float f1 = c_dec_hi[7 - u];
        // direct: r = j
        int num = j + 6 - u;
        if (num >= 0 && (num & 1) == 0) {
            int i = num >> 1;
            if (i < out) acc += f0 * lo[i * 16 + hw] + f1 * hi[i * 16 + hw];
        }
        // left reflect: r = -j (needs j in 1..6)
        if (j > 0 && j <= 6) {
            int num2 = -j + 6 - u;
            if (num2 >= 0 && (num2 & 1) == 0) {
                int i = num2 >> 1;
                if (i < out) acc += f0 * lo[i * 16 + hw] + f1 * hi[i * 16 + hw];
            }
        }
        // right reflect: r = 2N-2-j (needs r >= N)
        int rr = 2 * N - 2 - j;
        if (rr >= N) {
            int num3 = rr + 6 - u;
            if ((num3 & 1) == 0) {
                int i = num3 >> 1;
                if (i >= 0 && i < out)
                    acc += f0 * lo[i * 16 + hw] + f1 * hi[i * 16 + hw];
            }
        }
    }
    return acc;
}

// ============================================================
// Weight builder via adjoint DWT: Weff[bf] = M^T * conv_w[bf].
// 192 independent blocks (one per bf) x 256 threads; ~3us total.
// Coefficient layout in w (154): lo4 @0(14), hi1 @14(67),
// hi2 @81(37), hi3 @118(22), hi4 @140(14).
// Synthesis chain: (lo4,hi4)->y22 ->(hi3)->y37 ->(hi2)->y67
// ->(hi1)-> y128 = Weff row (k = j*16 + hw).
// ============================================================
__global__ void fold_adjoint(const float* __restrict__ conv_w) {
    __shared__ float Ws[TLEN * 16];
    __shared__ float y22[22 * 16];
    __shared__ float y37[37 * 16];
    __shared__ float y67[67 * 16];
    const int bf = blockIdx.x;
    const int tid = threadIdx.x;

    for (int i = tid; i < TLEN * 16; i += 256)
        Ws[i] = conv_w[(size_t)bf * (TLEN * 16) + i];
    __syncthreads();

    // level 4 adjoint: N=22, out=14, lo = w[0..14), hi = w[140..154)
    for (int idx = tid; idx < 22 * 16; idx += 256) {
        int j = idx >> 4, hw = idx & 15;
        y22[idx] = adj_level(Ws, Ws + 140 * 16, 22, 14, j, hw);
    }
    __syncthreads();
    // level 3 adjoint: N=37, out=22, lo = y22, hi = w[118..140)
    for (int idx = tid; idx < 37 * 16; idx += 256) {
        int j = idx >> 4, hw = idx & 15;
        y37[idx] = adj_level(y22, Ws + 118 * 16, 37, 22, j, hw);
    }
    __syncthreads();
    // level 2 adjoint: N=67, out=37, lo = y37, hi = w[81..118)
    for (int idx = tid; idx < 67 * 16; idx += 256) {
        int j = idx >> 4, hw = idx & 15;
        y67[idx] = adj_level(y37, Ws + 81 * 16, 67, 37, j, hw);
    }
    __syncthreads();
    // level 1 adjoint: N=128, out=67, lo = y67, hi = w[14..81)
    for (int idx = tid; idx < 128 * 16; idx += 256) {
        int j = idx >> 4, hw = idx & 15;
        g_Weff[(size_t)bf * KTOT + idx] =
            adj_level(y67, Ws + 14 * 16, 128, 67, j, hw);
    }
}

// ============================================================
// Producer pieces (R9 verbatim). One chunk = 512 k x 16 n,
// filled in 2 waves of 4 np, 16 front-batched LDG.128 per wave.
// Slot layout (floats): buf[np*1024 + 2*k + hal], k0 even.
// ============================================================
__device__ __forceinline__ void ldnp(const float* __restrict__ x,
                                     int b, int g, int ci, int ntot,
                                     int ptid, int np,
                                     float4* v0, float4* v1)
{
    int ne = g * NT + 2 * np;
    int no = ne + 1;
    if (ne >= ntot) ne = ntot - 1;
    if (no >= ntot) no = ntot - 1;
    const float4* xg0 = reinterpret_cast<const float4*>(
        x + ((size_t)ne * 512 + b * 128 + ci * 32) * 64);
    const float4* xg1 = reinterpret_cast<const float4*>(
        x + ((size_t)no * 512 + b * 128 + ci * 32) * 64);
    v0[0] = xg0[ptid];       v0[1] = xg0[ptid + 256];
    v1[0] = xg1[ptid];       v1[1] = xg1[ptid + 256];
}

__device__ __forceinline__ void poolstore(float* __restrict__ smp, int ptid,
                                          const float4* v0, const float4* v1)
{
    #pragma unroll
    for (int r = 0; r < 2; ++r) {
        int slot = ptid + 256 * r;
        float a0 = fmaxf(v0[r].x, v0[r].y), c0 = fmaxf(v0[r].z, v0[r].w);
        float a1 = fmaxf(v1[r].x, v1[r].y), c1 = fmaxf(v1[r].z, v1[r].w);
        a0 = fmaxf(a0, __shfl_xor_sync(0xffffffffu, a0, 2));
        c0 = fmaxf(c0, __shfl_xor_sync(0xffffffffu, c0, 2));
        a1 = fmaxf(a1, __shfl_xor_sync(0xffffffffu, a1, 2));
        c1 = fmaxf(c1, __shfl_xor_sync(0xffffffffu, c1, 2));
        if ((slot & 2) == 0) {
            int tl = slot >> 4;
            int h  = (slot >> 2) & 3;
            int qh = slot & 1;
            int k0 = tl * 16 + h * 4 + 2 * qh;
            *reinterpret_cast<float4*>(smp + 2 * k0) =
                make_float4(a0, a1, c0, c1);
        }
    }
}

__device__ __forceinline__ void produce(float* __restrict__ buf,
                                        const float* __restrict__ x,
                                        int b, int g, int ci,
                                        int ntot, int ptid)
{
    #pragma unroll
    for (int wv = 0; wv < 2; ++wv) {
        float4 v0[4][2], v1[4][2];
        #pragma unroll
        for (int i = 0; i < 4; ++i)
            ldnp(x, b, g, ci, ntot, ptid, wv * 4 + i, v0[i], v1[i]);
        #pragma unroll
        for (int i = 0; i < 4; ++i)
            poolstore(buf + (wv * 4 + i) * 1024, ptid, v0[i], v1[i]);
    }
}

// ============================================================
// Main (R9 verbatim): persistent, warp-specialized, 4-slot ring.
// 148 CTAs x 768 threads, 128KB smem.
// Warps 0..15: consumers (3 feats, 8 planes); 16..23: producers.
// ============================================================
__global__ __launch_bounds__(NTHREADS, 1)
void dwt_main_kernel(const float* __restrict__ x,
                     const float* __restrict__ conv_b,
                     float* __restrict__ out, int ntot, int groups)
{
    extern __shared__ float sm[];
    const int tid  = threadIdx.x;
    const int warp = tid >> 5;
    const int lane = tid & 31;
    const int cta  = blockIdx.x;
    const int G    = gridDim.x;
    const int nunits = NBINS * groups;
    const int myUnits = (cta < nunits) ? ((nunits - 1 - cta) / G + 1) : 0;
    const int totalChunks = CPU * myUnits;

    u64 acc[3][8];
    #pragma unroll
    for (int f = 0; f < 3; ++f)
        #pragma unroll
        for (int p = 0; p < 8; ++p) acc[f][p] = 0ull;

    if (warp < 16) {
        #pragma unroll
        for (int s = 0; s < NSLOTS; ++s) BAR_ARRIVE(5 + s);
    }

    if (warp >= 16) {
        // ================= producers =================
        const int ptid = tid - 512;
        for (int sc = 0; sc < totalChunks; ++sc) {
            const int slot = sc & 3;
            const int u  = cta + G * (sc >> 2);
            const int b  = u / groups;
            const int g  = u % groups;
            const int ci = sc & 3;
            BAR_SYNC(5 + slot);
            produce(sm + slot * SLOTF, x, b, g, ci, ntot, ptid);
            BAR_ARRIVE(1 + slot);
        }
    } else {
        // ================= consumers =================
        for (int sc = 0; sc < totalChunks; ++sc) {
            const int slot = sc & 3;
            const int u  = cta + G * (sc >> 2);
            const int b  = u / groups;
            const int g  = u % groups;
            const int ci = sc & 3;
            float* buf = sm + slot * SLOTF;

            BAR_SYNC(1 + slot);

            const float* Wb = g_Weff + ((size_t)(b * NFEAT + warp * 3)) * KTOT
                              + ci * CHUNKK + lane;
            const float* smk = buf + 2 * lane;

            float w0[3], w1[3];
            #pragma unroll
            for (int f = 0; f < 3; ++f) w0[f] = __ldg(Wb + f * KTOT);
            #pragma unroll
            for (int f = 0; f < 3; ++f) w1[f] = __ldg(Wb + f * KTOT + 32);

            #pragma unroll 1
            for (int jl = 0; jl < 16; jl += 2) {
                {   // even jl: use w0, prefetch jl+2
                    u64 p2[8];
                    #pragma unroll
                    for (int pl = 0; pl < 8; ++pl)
                        p2[pl] = *reinterpret_cast<const u64*>(
                            smk + pl * 1024 + 64 * jl);
                    float a0 = w0[0], a1 = w0[1], a2 = w0[2];
                    if (jl + 2 < 16) {
                        #pragma unroll
                        for (int f = 0; f < 3; ++f)
                            w0[f] = __ldg(Wb + f * KTOT + 32 * (jl + 2));
                    }
                    u64 d0 = dup2(a0), d1 = dup2(a1), d2 = dup2(a2);
                    #pragma unroll
                    for (int pl = 0; pl < 8; ++pl) {
                        acc[0][pl] = ffma2(d0, p2[pl], acc[0][pl]);
                        acc[1][pl] = ffma2(d1, p2[pl], acc[1][pl]);
                        acc[2][pl] = ffma2(d2, p2[pl], acc[2][pl]);
                    }
                }
                {   // odd jl: use w1, prefetch jl+3
                    u64 p2[8];
                    #pragma unroll
                    for (int pl = 0; pl < 8; ++pl)
                        p2[pl] = *reinterpret_cast<const u64*>(
                            smk + pl * 1024 + 64 * (jl + 1));
                    float a0 = w1[0], a1 = w1[1], a2 = w1[2];
                    if (jl + 3 < 16) {
                        #pragma unroll
                        for (int f = 0; f < 3; ++f)
                            w1[f] = __ldg(Wb + f * KTOT + 32 * (jl + 3));
                    }
                    u64 d0 = dup2(a0), d1 = dup2(a1), d2 = dup2(a2);
                    #pragma unroll
                    for (int pl = 0; pl < 8; ++pl) {
                        acc[0][pl] = ffma2(d0, p2[pl], acc[0][pl]);
                        acc[1][pl] = ffma2(d1, p2[pl], acc[1][pl]);
                        acc[2][pl] = ffma2(d2, p2[pl], acc[2][pl]);
                    }
                }
            }

            BAR_ARRIVE(5 + slot);

            if (ci == CPU - 1) {
                #pragma unroll
                for (int off = 16; off; off >>= 1)
                    #pragma unroll
                    for (int f = 0; f < 3; ++f)
                        #pragma unroll
                        for (int pl = 0; pl < 8; ++pl)
                            acc[f][pl] = fadd2(acc[f][pl],
                                __shfl_xor_sync(0xffffffffu, acc[f][pl], off));
                if (lane == 0) {
                    int n0 = g * NT;
                    #pragma unroll
                    for (int f = 0; f < 3; ++f) {
                        int fgl = warp * 3 + f;
                        float bias = conv_b[b * NFEAT + fgl];
                        #pragma unroll
                        for (int pl = 0; pl < 8; ++pl) {
                            float2 v = unpack2(acc[f][pl]);
                            int na = n0 + 2 * pl;
                            float ya = v.x + bias; ya = (ya > 0.0f) ? ya : 0.02f * ya;
                            float yb = v.y + bias; yb = (yb > 0.0f) ? yb : 0.02f * yb;
                            if (na < ntot)
                                out[(size_t)na * OUTF + b * NFEAT + fgl] = ya;
                            if (na + 1 < ntot)
                                out[(size_t)(na + 1) * OUTF + b * NFEAT + fgl] = yb;
                        }
                    }
                }
                #pragma unroll
                for (int f = 0; f < 3; ++f)
                    #pragma unroll
                    for (int pl = 0; pl < 8; ++pl) acc[f][pl] = 0ull;
            }
        }
    }
}

// ============================================================
extern "C" void kernel_launch(void* const* d_in, const int* in_sizes, int n_in,
                              void* d_out, int out_size)
{
    const float* x      = (const float*)d_in[0];  // (n,1,512,8,8)
    const float* conv_w = (const float*)d_in[1];  // (4,48,154,4,4)
    const float* conv_b = (const float*)d_in[2];  // (4,48)
    float* out = (float*)d_out;                   // (n,192)

    int ntot   = in_sizes[0] / (512 * 64);
    int groups = (ntot + NT - 1) / NT;

    fold_adjoint<<<NBINS * NFEAT, 256>>>(conv_w);

    cudaFuncSetAttribute(dwt_main_kernel,
                         cudaFuncAttributeMaxDynamicSharedMemorySize,
                         NSLOTS * SLOTF * 4);
    dwt_main_kernel<<<NCTAS, NTHREADS, NSLOTS * SLOTF * 4>>>(x, conv_b, out, ntot, groups);
}